// round 5
// baseline (speedup 1.0000x reference)
#include <cuda_runtime.h>
#include <math_constants.h>

// Statically-initialized accumulators; the last block resets them after use,
// so every graph replay sees zeros. No cudaMalloc, no extra launches.
__device__ double g_eme_sum = 0.0;
__device__ unsigned int g_eme_count = 0u;

// One thread per 8x8 window. Input logical shape (32,3,1024,1024) fp32,
// treated as 96 images of 1024x1024. Windows per image: 128x128.
// Grid: 6144 blocks x 256 threads = 1,572,864 windows exactly.
// min-blocks 7 -> 36-reg budget: room for an 8x LDG.128 front-batch while
// keeping 56 resident warps/SM.
__global__ __launch_bounds__(256, 7) void eme_fused_kernel(
    const float* __restrict__ y, float* __restrict__ out)
{
    const int w = blockIdx.x * 256 + threadIdx.x;

    const int img = w >> 14;          // 16384 windows per image
    const int rem = w & 16383;
    const int wy  = rem >> 7;         // window row 0..127
    const int wx  = rem & 127;        // window col 0..127

    const float4* __restrict__ p = reinterpret_cast<const float4*>(
        y + (size_t)img * 1048576u + (size_t)wy * 8192u + (size_t)wx * 8u);
    // image row stride = 1024 floats = 256 float4

    float mx = -CUDART_INF_F;
    float mn =  CUDART_INF_F;

    // Two half-windows of 4 rows each: load all 8 float4 of a half first
    // (8 independent LDG.128 batched back-to-back), then reduce.
    #pragma unroll
    for (int h = 0; h < 2; h++) {
        float4 v[8];
        #pragma unroll
        for (int r = 0; r < 4; r++) {
            v[2 * r]     = __ldcs(&p[(h * 4 + r) * 256]);
            v[2 * r + 1] = __ldcs(&p[(h * 4 + r) * 256 + 1]);
        }
        #pragma unroll
        for (int i = 0; i < 8; i++) {
            mx = fmaxf(mx, fmaxf(fmaxf(v[i].x, v[i].y), fmaxf(v[i].z, v[i].w)));
            mn = fminf(mn, fminf(fminf(v[i].x, v[i].y), fminf(v[i].z, v[i].w)));
        }
    }

    float val = 0.0f;
    if (mx != mn) {
        val = 20.0f * logf(mx / (mn + 1e-4f));
    }

    // Intra-warp reduction.
    #pragma unroll
    for (int o = 16; o > 0; o >>= 1)
        val += __shfl_xor_sync(0xffffffffu, val, o);

    __shared__ float warp_sums[8];
    const int lane = threadIdx.x & 31;
    const int wid  = threadIdx.x >> 5;
    if (lane == 0) warp_sums[wid] = val;
    __syncthreads();

    if (wid == 0) {
        float v = (lane < 8) ? warp_sums[lane] : 0.0f;
        #pragma unroll
        for (int o = 4; o > 0; o >>= 1)
            v += __shfl_xor_sync(0xffffffffu, v, o);

        if (lane == 0) {
            atomicAdd(&g_eme_sum, (double)v);
            __threadfence();
            unsigned int done = atomicAdd(&g_eme_count, 1u);
            if (done == gridDim.x - 1u) {
                // All partials visible (each block fenced before incrementing).
                double s = g_eme_sum;
                // result = sum / (B * row * col / (w*w)) = sum / 524288
                out[0] = (float)(s * (1.0 / 524288.0));
                // Reset for the next graph replay.
                g_eme_sum = 0.0;
                g_eme_count = 0u;
            }
        }
    }
}

extern "C" void kernel_launch(void* const* d_in, const int* in_sizes, int n_in,
                              void* d_out, int out_size)
{
    const float* y = (const float*)d_in[0];
    float* out = (float*)d_out;

    const int n_windows = 32 * 3 * 128 * 128;  // 1,572,864
    const int threads = 256;
    const int blocks = n_windows / threads;    // 6144, exact

    eme_fused_kernel<<<blocks, threads>>>(y, out);
}

// round 6
// speedup vs baseline: 1.0041x; 1.0041x over previous
#include <cuda_runtime.h>
#include <math_constants.h>

// Statically-initialized accumulators; the last block resets them after use,
// so every graph replay sees zeros. No cudaMalloc, no extra launches.
__device__ double g_eme_sum = 0.0;
__device__ unsigned int g_eme_count = 0u;

// One thread per 8x8 window. Input logical shape (32,3,1024,1024) fp32,
// treated as 96 images of 1024x1024. Windows per image: 128x128.
// Grid: 3072 blocks x 512 threads = 1,572,864 windows exactly.
// min-blocks 3 -> ~40 reg budget so ptxas can front-batch 8 LDG.128 per half.
__global__ __launch_bounds__(512, 3) void eme_fused_kernel(
    const float* __restrict__ y, float* __restrict__ out)
{
    const int w = blockIdx.x * 512 + threadIdx.x;

    const int img = w >> 14;          // 16384 windows per image
    const int rem = w & 16383;
    const int wy  = rem >> 7;         // window row 0..127
    const int wx  = rem & 127;        // window col 0..127

    const float4* __restrict__ p = reinterpret_cast<const float4*>(
        y + (size_t)img * 1048576u + (size_t)wy * 8192u + (size_t)wx * 8u);
    // image row stride = 1024 floats = 256 float4

    float mx = -CUDART_INF_F;
    float mn =  CUDART_INF_F;

    // Two half-windows of 4 rows each: load all 8 float4 of a half first
    // (8 independent LDG.128 batched back-to-back), then reduce.
    #pragma unroll
    for (int h = 0; h < 2; h++) {
        float4 v[8];
        #pragma unroll
        for (int r = 0; r < 4; r++) {
            v[2 * r]     = __ldcs(&p[(h * 4 + r) * 256]);
            v[2 * r + 1] = __ldcs(&p[(h * 4 + r) * 256 + 1]);
        }
        #pragma unroll
        for (int i = 0; i < 8; i++) {
            mx = fmaxf(mx, fmaxf(fmaxf(v[i].x, v[i].y), fmaxf(v[i].z, v[i].w)));
            mn = fminf(mn, fminf(fminf(v[i].x, v[i].y), fminf(v[i].z, v[i].w)));
        }
    }

    float val = 0.0f;
    if (mx != mn) {
        val = 20.0f * logf(mx / (mn + 1e-4f));
    }

    // Intra-warp reduction.
    #pragma unroll
    for (int o = 16; o > 0; o >>= 1)
        val += __shfl_xor_sync(0xffffffffu, val, o);

    __shared__ float warp_sums[16];
    const int lane = threadIdx.x & 31;
    const int wid  = threadIdx.x >> 5;
    if (lane == 0) warp_sums[wid] = val;
    __syncthreads();

    if (wid == 0) {
        float v = (lane < 16) ? warp_sums[lane] : 0.0f;
        #pragma unroll
        for (int o = 8; o > 0; o >>= 1)
            v += __shfl_xor_sync(0xffffffffu, v, o);

        if (lane == 0) {
            atomicAdd(&g_eme_sum, (double)v);
            __threadfence();
            unsigned int done = atomicAdd(&g_eme_count, 1u);
            if (done == gridDim.x - 1u) {
                // All partials visible (each block fenced before incrementing).
                double s = g_eme_sum;
                // result = sum / (B * row * col / (w*w)) = sum / 524288
                out[0] = (float)(s * (1.0 / 524288.0));
                // Reset for the next graph replay.
                g_eme_sum = 0.0;
                g_eme_count = 0u;
            }
        }
    }
}

extern "C" void kernel_launch(void* const* d_in, const int* in_sizes, int n_in,
                              void* d_out, int out_size)
{
    const float* y = (const float*)d_in[0];
    float* out = (float*)d_out;

    const int n_windows = 32 * 3 * 128 * 128;  // 1,572,864
    const int threads = 512;
    const int blocks = n_windows / threads;    // 3072, exact

    eme_fused_kernel<<<blocks, threads>>>(y, out);
}

// round 7
// speedup vs baseline: 1.0114x; 1.0073x over previous
#include <cuda_runtime.h>
#include <math_constants.h>

// Statically-initialized accumulators; the last block resets them after use,
// so every graph replay sees zeros. No cudaMalloc, no extra launches.
__device__ double g_eme_sum = 0.0;
__device__ unsigned int g_eme_count = 0u;

// One thread per 8x8 window. Input logical shape (32,3,1024,1024) fp32,
// treated as 96 images of 1024x1024. Windows per image: 128x128.
// Grid: 6144 blocks x 256 threads = 1,572,864 windows exactly.
// min-blocks 3 -> 85-reg budget: front-batch ALL 16 LDG.128 of the window
// (64 data regs) to maximize per-warp L1tex queue depth (MLP_p1 = 16).
__global__ __launch_bounds__(256, 3) void eme_fused_kernel(
    const float* __restrict__ y, float* __restrict__ out)
{
    const int w = blockIdx.x * 256 + threadIdx.x;

    const int img = w >> 14;          // 16384 windows per image
    const int rem = w & 16383;
    const int wy  = rem >> 7;         // window row 0..127
    const int wx  = rem & 127;        // window col 0..127

    const float4* __restrict__ p = reinterpret_cast<const float4*>(
        y + (size_t)img * 1048576u + (size_t)wy * 8192u + (size_t)wx * 8u);
    // image row stride = 1024 floats = 256 float4

    // Load the whole 8x8 window: 16 independent LDG.128 back-to-back.
    float4 v[16];
    #pragma unroll
    for (int r = 0; r < 8; r++) {
        v[2 * r]     = __ldcs(&p[r * 256]);
        v[2 * r + 1] = __ldcs(&p[r * 256 + 1]);
    }

    float mx = -CUDART_INF_F;
    float mn =  CUDART_INF_F;
    #pragma unroll
    for (int i = 0; i < 16; i++) {
        mx = fmaxf(mx, fmaxf(fmaxf(v[i].x, v[i].y), fmaxf(v[i].z, v[i].w)));
        mn = fminf(mn, fminf(fminf(v[i].x, v[i].y), fminf(v[i].z, v[i].w)));
    }

    float val = 0.0f;
    if (mx != mn) {
        val = 20.0f * logf(mx / (mn + 1e-4f));
    }

    // Intra-warp reduction.
    #pragma unroll
    for (int o = 16; o > 0; o >>= 1)
        val += __shfl_xor_sync(0xffffffffu, val, o);

    __shared__ float warp_sums[8];
    const int lane = threadIdx.x & 31;
    const int wid  = threadIdx.x >> 5;
    if (lane == 0) warp_sums[wid] = val;
    __syncthreads();

    if (wid == 0) {
        float vv = (lane < 8) ? warp_sums[lane] : 0.0f;
        #pragma unroll
        for (int o = 4; o > 0; o >>= 1)
            vv += __shfl_xor_sync(0xffffffffu, vv, o);

        if (lane == 0) {
            atomicAdd(&g_eme_sum, (double)vv);
            __threadfence();
            unsigned int done = atomicAdd(&g_eme_count, 1u);
            if (done == gridDim.x - 1u) {
                // All partials visible (each block fenced before incrementing).
                double s = g_eme_sum;
                // result = sum / (B * row * col / (w*w)) = sum / 524288
                out[0] = (float)(s * (1.0 / 524288.0));
                // Reset for the next graph replay.
                g_eme_sum = 0.0;
                g_eme_count = 0u;
            }
        }
    }
}

extern "C" void kernel_launch(void* const* d_in, const int* in_sizes, int n_in,
                              void* d_out, int out_size)
{
    const float* y = (const float*)d_in[0];
    float* out = (float*)d_out;

    const int n_windows = 32 * 3 * 128 * 128;  // 1,572,864
    const int threads = 256;
    const int blocks = n_windows / threads;    // 6144, exact

    eme_fused_kernel<<<blocks, threads>>>(y, out);
}